// round 9
// baseline (speedup 1.0000x reference)
#include <cuda_runtime.h>
#include <math.h>

// ---------------------------------------------------------------------------
// RoutingStorage (GR4J). Chunk-parallel scan with warmup. R8: warm-start the
// warmup from the estimated stationary store r^ (computed on-device from the
// mean inflow), skipping the ~100-step ramp that forced W=256. Wall law
// (measured): wall = (W+L) x iterCost(K); K=2 interleave is free (156cyc/iter)
// -> minimize W. Early region (t<512) keeps zero-start W=208 (exact for
// t0<=208, norm-diluted ~4e-3 local err for the 25 chains in (208,416)).
// ---------------------------------------------------------------------------

#define T_MAX 262144
constexpr int K_CH    = 2;     // chains per thread (interleaved)
constexpr int L       = 8;     // output steps per chain
constexpr int W_WARM  = 160;   // warmup for warm-started chains
constexpr int W_ZERO  = 208;   // warmup for block 0 (zero-start)
constexpr int FRONT   = W_ZERO;
constexpr int BACK    = 64;
constexpr int BLK     = 32;    // threads/block (1 warp)
constexpr int CPB     = BLK * K_CH;          // 64 chains/block
constexpr int OSZ     = CPB * L;             // 512 outputs/block
constexpr int WSZ     = W_ZERO + OSZ;        // 720 max window
constexpr int WSZP    = WSZ + WSZ / 32;
constexpr int OSZP    = OSZ + OSZ / 32;
constexpr int WARM_T0 = 416;   // chains with t0 >= this warm-start from r^

static __device__ float  g_c1[FRONT + T_MAX + BACK];
static __device__ float  g_c2[FRONT + T_MAX + BACK];
static __device__ float  g_partial[1200];
static __device__ float2 g_init;     // (z0 = r^+gw^, gw^)

__device__ __forceinline__ float fsqrt_approx(float x) {
    float y; asm("sqrt.approx.f32 %0, %1;" : "=f"(y) : "f"(x)); return y;
}
__device__ __forceinline__ int padi(int d) { return d + (d >> 5); }

// Unit-hydrograph ordinates for X4 = 2.5:
__constant__ float c_o1[3] = {0.10119288512538814f, 0.47124051711455807f,
                              0.42756659776005380f};
__constant__ float c_o2[6] = {0.05059644256269407f, 0.23562025855727903f,
                              0.42756659776005380f, 0.23562025855727903f,
                              0.05059644256269407f, 0.0f};

__global__ void conv_kernel(const float* __restrict__ x, int T, int NTOT) {
    int i = blockIdx.x * 256 + threadIdx.x;
    int t = i - FRONT;
    float c1 = 0.0f, c2 = 0.0f;
    if (i < NTOT && t >= 0 && t < T) {
#pragma unroll
        for (int j = 0; j < 6; ++j) {
            int idx = t - j;
            if (idx >= 0) {
                float4 row = *reinterpret_cast<const float4*>(x + 4 * idx);
                float pr = row.w + (row.x - row.z);   // perc + (p_n - p_s)
                if (j < 3) c1 += c_o1[j] * (0.9f * pr);
                c2 += c_o2[j] * (0.1f * pr);
            }
        }
    }
    if (i < NTOT) { g_c1[i] = c1; g_c2[i] = c2; }
    // Deterministic per-block sum of c1 (pads contribute 0).
    __shared__ float red[256];
    red[threadIdx.x] = c1;
    __syncthreads();
#pragma unroll
    for (int s = 128; s > 0; s >>= 1) {
        if (threadIdx.x < s) red[threadIdx.x] += red[threadIdx.x + s];
        __syncthreads();
    }
    if (threadIdx.x == 0) g_partial[blockIdx.x] = red[0];
}

// Deterministic reduce of partials -> mean inflow m -> fixed-point for r*.
__global__ void solve_kernel(const float* __restrict__ x2p,
                             const float* __restrict__ x3p,
                             int T, int nparts) {
    __shared__ float red[256];
    float s = 0.0f;
    for (int i = threadIdx.x; i < nparts; i += 256) s += g_partial[i];
    red[threadIdx.x] = s;
    __syncthreads();
#pragma unroll
    for (int w = 128; w > 0; w >>= 1) {
        if (threadIdx.x < w) red[threadIdx.x] += red[threadIdx.x + w];
        __syncthreads();
    }
    if (threadIdx.x == 0) {
        float m  = red[0] / (float)T;
        float x2 = x2p[0], x3 = x3p[0];
        float r = 20.0f;
        for (int it = 0; it < 400; ++it) {
            float gw = x2 * powf(r / x3, 3.5f);
            float sv = fmaxf(r + m + gw, 0.0f);
            float u  = powf(sv / x3, 4.0f);
            r = sv * powf(1.0f + u, -0.25f);
        }
        float gw0 = x2 * powf(r / x3, 3.5f);
        g_init = make_float2(r + gw0, gw0);
    }
}

// (1+u)^(-1/4) deg-4 Horner
#define P1 (-0.25f)
#define P2 ( 0.15625f)
#define P3 (-0.1171875f)
#define P4 ( 0.0952148438f)
// (1+u)^(-7/8) deg-3 Horner (off-critical gw branch)
#define Q1 (-0.875f)
#define Q2 ( 0.8203125f)
#define Q3 (-0.7861328125f)

// Stage-ordered dual-chain step core (no stores). Updates za,gwa,zb,gwb and
// exposes sa,sb,rna,rnb for the output phase.
#define DUAL_STEP(c1a, c1b)                                            \
    float sa  = fmaxf(za + c1a, 0.0f), sb  = fmaxf(zb + c1b, 0.0f);    \
    float va  = sa * kx,               vb  = sb * kx;                  \
    float sva = fsqrt_approx(va),      svb = fsqrt_approx(vb);         \
    float aa  = sa * sa,               ab  = sb * sb;                  \
    float ua  = (aa * inv4) * aa,      ub  = (ab * inv4) * ab;         \
    float pa  = fmaf(ua, P4, P3),      pb  = fmaf(ub, P4, P3);         \
    pa = fmaf(ua, pa, P2);             pb = fmaf(ub, pb, P2);          \
    pa = fmaf(ua, pa, P1);             pb = fmaf(ub, pb, P1);          \
    pa = fmaf(ua, pa, 1.0f);           pb = fmaf(ub, pb, 1.0f);        \
    float qa = fmaf(ua, Q3, Q2),       qb = fmaf(ub, Q3, Q2);          \
    qa = fmaf(ua, qa, Q1);             qb = fmaf(ub, qb, Q1);          \
    qa = fmaf(ua, qa, 1.0f);           qb = fmaf(ub, qb, 1.0f);        \
    float ga  = ((va * va) * va) * sva, gb = ((vb * vb) * vb) * svb;   \
    float rna = sa * pa,               rnb = sb * pb;                  \
    gwa = ga * qa;                     gwb = gb * qb;                  \
    za  = rna + gwa;                   zb  = rnb + gwb;

__global__ void __launch_bounds__(BLK, 1)
scan_kernel(const float* __restrict__ x2p,
            const float* __restrict__ x3p,
            float* __restrict__ out, int T) {
    __shared__ float s1[WSZP];
    __shared__ float s2[WSZP];
    __shared__ float sq[OSZP];
    __shared__ float sr[OSZP];

    int tid = threadIdx.x;
    int b   = blockIdx.x;
    int t0b = b * OSZ;
    if (t0b >= T) return;

    const int Wb  = (b == 0) ? W_ZERO : W_WARM;
    const int wsz = Wb + OSZ;
    // Window: chain lc reads times [t0 - Wb, t0 + L); g index = gbase + d.
    {
        int gbase = t0b + FRONT - Wb;
        const float* g1 = g_c1 + gbase;
        const float* g2 = g_c2 + gbase;
        for (int d = tid; d < wsz; d += BLK) {
            s1[padi(d)] = g1[d];
            s2[padi(d)] = g2[d];
        }
    }
    __syncthreads();

    const float x2  = __ldg(x2p);
    const float x3  = __ldg(x3p);
    const float inv = 1.0f / x3;
    const float inv2 = inv * inv, inv4 = inv2 * inv2;
    const float kx  = __powf(x2, 0.2857142857f) * inv;   // x2^(2/7)/x3

    // Chain A = lc tid (t0 = t0b + 8*tid), chain B = lc tid+32 (t0 + 256).
    const int da0 = tid * L;
    const int db0 = da0 + 256;
    const int t0a = t0b + da0;
    const int t0bb = t0a + 256;

    float2 init = g_init;
    float za, gwa, zb, gwb;
    if (t0a  >= WARM_T0) { za = init.x; gwa = init.y; } else { za = 0.0f; gwa = 0.0f; }
    if (t0bb >= WARM_T0) { zb = init.x; gwb = init.y; } else { zb = 0.0f; gwb = 0.0f; }

    // ---- Warmup ----
#pragma unroll 4
    for (int i = 0; i < Wb; ++i) {
        float c1a = s1[padi(da0 + i)];
        float c1b = s1[padi(db0 + i)];
        DUAL_STEP(c1a, c1b)
        (void)rna; (void)rnb;
    }

    // ---- Output phase ----
#pragma unroll
    for (int j = 0; j < L; ++j) {
        int ia = da0 + Wb + j, ib = db0 + Wb + j;
        float c1a = s1[padi(ia)], c2a = s2[padi(ia)];
        float c1b = s1[padi(ib)], c2b = s2[padi(ib)];
        float qda = fmaxf(c2a + gwa, 0.0f);   // uses OLD gw
        float qdb = fmaxf(c2b + gwb, 0.0f);
        DUAL_STEP(c1a, c1b)
        sq[padi(da0 + j)] = (sa - rna) + qda;
        sr[padi(da0 + j)] = rna;
        sq[padi(db0 + j)] = (sb - rnb) + qdb;
        sr[padi(db0 + j)] = rnb;
    }
    __syncthreads();

    // ---- Coalesced epilogue ----
    float* __restrict__ qout = out;        // qsim    [0, T)
    float* __restrict__ rout = out + T;    // r_store [T, 2T)
    int lim = T - t0b; if (lim > OSZ) lim = OSZ;
    for (int d = tid; d < lim; d += BLK) {
        qout[t0b + d] = sq[padi(d)];
        rout[t0b + d] = sr[padi(d)];
    }
}

extern "C" void kernel_launch(void* const* d_in, const int* in_sizes, int n_in,
                              void* d_out, int out_size) {
    const float* x  = (const float*)d_in[0];
    const float* x2 = (const float*)d_in[1];
    const float* x3 = (const float*)d_in[2];
    int T = in_sizes[0] / 4;
    if (T > T_MAX) T = T_MAX;

    int NTOT = FRONT + T + BACK;
    int cblocks = (NTOT + 255) / 256;
    conv_kernel<<<cblocks, 256>>>(x, T, NTOT);
    solve_kernel<<<1, 256>>>(x2, x3, T, cblocks);

    int nblocks = (T + OSZ - 1) / OSZ;     // 512 for T = 262144
    scan_kernel<<<nblocks, BLK>>>(x2, x3, (float*)d_out, T);
}

// round 13
// speedup vs baseline: 6.7130x; 6.7130x over previous
#include <cuda_runtime.h>
#include <math.h>

// ---------------------------------------------------------------------------
// RoutingStorage (GR4J). Chunk-parallel scan, warm-started warmup.
// R12 = R9's PROVEN accuracy scheme (W_ZERO=208 for block0, W_WARM=160,
// warm-start only chains with t0>=416 -- protects the no-contraction ramp
// region that sank R11) + R10's fast auxiliaries (sampled-mean solve, 64
// approx fixed-point iters) + software-pipelined c1 loads in the warmup
// loop (removes a naked 29-cyc LDS exposure per iteration; iterCost
// 156 -> ~120 predicted).
// ---------------------------------------------------------------------------

#define T_MAX 262144
constexpr int L       = 8;     // output steps per chain
constexpr int W_WARM  = 160;   // warmup, warm-started blocks (b >= 1)
constexpr int W_ZERO  = 208;   // warmup, block 0 (zero-start region)
constexpr int FRONT   = W_ZERO;
constexpr int BACK    = 64;
constexpr int BLK     = 32;    // threads/block (1 warp), 2 chains/thread
constexpr int CPB     = BLK * 2;             // 64 chains/block
constexpr int OSZ     = CPB * L;             // 512 outputs/block
constexpr int WSZ     = W_ZERO + OSZ;        // 720 max window
constexpr int WSZP    = WSZ + WSZ / 32;
constexpr int OSZP    = OSZ + OSZ / 32;
constexpr int WARM_T0 = 416;   // chains with t0 >= this warm-start from r^

static __device__ float  g_c1[FRONT + T_MAX + BACK];
static __device__ float  g_c2[FRONT + T_MAX + BACK];
static __device__ float2 g_init;     // (z0 = r^+gw^, gw^)

__device__ __forceinline__ float fsqrt_approx(float x) {
    float y; asm("sqrt.approx.f32 %0, %1;" : "=f"(y) : "f"(x)); return y;
}
__device__ __forceinline__ int padi(int d) { return d + (d >> 5); }

// Unit-hydrograph ordinates for X4 = 2.5:
__constant__ float c_o1[3] = {0.10119288512538814f, 0.47124051711455807f,
                              0.42756659776005380f};
__constant__ float c_o2[6] = {0.05059644256269407f, 0.23562025855727903f,
                              0.42756659776005380f, 0.23562025855727903f,
                              0.05059644256269407f, 0.0f};

__global__ void conv_kernel(const float* __restrict__ x, int T, int NTOT) {
    int i = blockIdx.x * 256 + threadIdx.x;
    if (i >= NTOT) return;
    int t = i - FRONT;
    if (t < 0 || t >= T) { g_c1[i] = 0.0f; g_c2[i] = 0.0f; return; }
    float c1 = 0.0f, c2 = 0.0f;
#pragma unroll
    for (int j = 0; j < 6; ++j) {
        int idx = t - j;
        if (idx >= 0) {
            float4 row = *reinterpret_cast<const float4*>(x + 4 * idx);
            float pr = row.w + (row.x - row.z);   // perc + (p_n - p_s)
            if (j < 3) c1 += c_o1[j] * (0.9f * pr);
            c2 += c_o2[j] * (0.1f * pr);
        }
    }
    g_c1[i] = c1; g_c2[i] = c2;
}

// (1+u)^(-1/4) deg-4 Horner
#define P1 (-0.25f)
#define P2 ( 0.15625f)
#define P3 (-0.1171875f)
#define P4 ( 0.0952148438f)
// (1+u)^(-7/8) deg-3 Horner (off-critical gw branch)
#define Q1 (-0.875f)
#define Q2 ( 0.8203125f)
#define Q3 (-0.7861328125f)

// Sampled mean inflow -> fast approx fixed-point for the stationary store.
__global__ void solve_kernel(const float* __restrict__ x2p,
                             const float* __restrict__ x3p, int T) {
    __shared__ float red[256];
    int nsamp = T / 64; if (nsamp < 1) nsamp = 1;
    float s = 0.0f;
    for (int k = threadIdx.x; k < nsamp; k += 256)
        s += g_c1[FRONT + 64 * k];
    red[threadIdx.x] = s;
    __syncthreads();
#pragma unroll
    for (int w = 128; w > 0; w >>= 1) {
        if (threadIdx.x < w) red[threadIdx.x] += red[threadIdx.x + w];
        __syncthreads();
    }
    if (threadIdx.x == 0) {
        float m   = red[0] / (float)nsamp;
        float x2  = x2p[0], x3 = x3p[0];
        float inv = 1.0f / x3;
        float inv2 = inv * inv, inv4 = inv2 * inv2;
        float kx  = __powf(x2, 0.2857142857f) * inv;
        float z = 30.0f, gw = 0.0f;
        for (int it = 0; it < 64; ++it) {
            float sv_ = fmaxf(z + m, 0.0f);
            float v   = sv_ * kx;
            float sq  = fsqrt_approx(v);
            float a   = sv_ * sv_;
            float u   = (a * inv4) * a;
            float p   = fmaf(u, P4, P3); p = fmaf(u, p, P2);
            p = fmaf(u, p, P1); p = fmaf(u, p, 1.0f);
            float qq  = fmaf(u, Q3, Q2);
            qq = fmaf(u, qq, Q1); qq = fmaf(u, qq, 1.0f);
            float rn  = sv_ * p;
            gw = (((v * v) * v) * sq) * qq;
            z  = rn + gw;
        }
        g_init = make_float2(z, gw);
    }
}

// Stage-ordered dual-chain step core. Updates za,gwa,zb,gwb;
// exposes sa,sb,rna,rnb. (R9-proven numerics — unchanged.)
#define DUAL_STEP(c1a, c1b)                                            \
    float sa  = fmaxf(za + c1a, 0.0f), sb  = fmaxf(zb + c1b, 0.0f);    \
    float va  = sa * kx,               vb  = sb * kx;                  \
    float sva = fsqrt_approx(va),      svb = fsqrt_approx(vb);         \
    float aa  = sa * sa,               ab  = sb * sb;                  \
    float ua  = (aa * inv4) * aa,      ub  = (ab * inv4) * ab;         \
    float pa  = fmaf(ua, P4, P3),      pb  = fmaf(ub, P4, P3);         \
    pa = fmaf(ua, pa, P2);             pb = fmaf(ub, pb, P2);          \
    pa = fmaf(ua, pa, P1);             pb = fmaf(ub, pb, P1);          \
    pa = fmaf(ua, pa, 1.0f);           pb = fmaf(ub, pb, 1.0f);        \
    float qa = fmaf(ua, Q3, Q2),       qb = fmaf(ub, Q3, Q2);          \
    qa = fmaf(ua, qa, Q1);             qb = fmaf(ub, qb, Q1);          \
    qa = fmaf(ua, qa, 1.0f);           qb = fmaf(ub, qb, 1.0f);        \
    float ga  = ((va * va) * va) * sva, gb = ((vb * vb) * vb) * svb;   \
    float rna = sa * pa,               rnb = sb * pb;                  \
    gwa = ga * qa;                     gwb = gb * qb;                  \
    za  = rna + gwa;                   zb  = rnb + gwb;

__global__ void __launch_bounds__(BLK, 1)
scan_kernel(const float* __restrict__ x2p,
            const float* __restrict__ x3p,
            float* __restrict__ out, int T) {
    __shared__ float s1[WSZP];
    __shared__ float s2[WSZP];
    __shared__ float sq[OSZP];
    __shared__ float sr[OSZP];

    int tid = threadIdx.x;
    int b   = blockIdx.x;
    int t0b = b * OSZ;
    if (t0b >= T) return;

    const int Wb  = (b == 0) ? W_ZERO : W_WARM;
    const int wsz = Wb + OSZ;
    {
        int gbase = t0b + FRONT - Wb;
        const float* g1 = g_c1 + gbase;
        const float* g2 = g_c2 + gbase;
        for (int d = tid; d < wsz; d += BLK) {
            s1[padi(d)] = g1[d];
            s2[padi(d)] = g2[d];
        }
    }
    __syncthreads();

    const float x2  = __ldg(x2p);
    const float x3  = __ldg(x3p);
    const float inv = 1.0f / x3;
    const float inv2 = inv * inv, inv4 = inv2 * inv2;
    const float kx  = __powf(x2, 0.2857142857f) * inv;   // x2^(2/7)/x3

    // Chain A: t0 = t0b + 8*tid; chain B: t0 + 256.
    const int da0 = tid * L;
    const int db0 = da0 + 256;
    const int t0a = t0b + da0;
    const int t0c = t0a + 256;

    float2 init = g_init;
    float za, gwa, zb, gwb;
    if (t0a >= WARM_T0) { za = init.x; gwa = init.y; } else { za = 0.0f; gwa = 0.0f; }
    if (t0c >= WARM_T0) { zb = init.x; gwb = init.y; } else { zb = 0.0f; gwb = 0.0f; }

    // ---- Warmup: software-pipelined c1 loads (prefetch depth 1) ----
    float n1a = s1[padi(da0)];
    float n1b = s1[padi(db0)];
#pragma unroll 4
    for (int i = 0; i < Wb; ++i) {
        float c1a = n1a, c1b = n1b;
        n1a = s1[padi(da0 + i + 1)];      // next iter's inputs: LDS latency
        n1b = s1[padi(db0 + i + 1)];      // overlaps this iter's math
        DUAL_STEP(c1a, c1b)
        (void)rna; (void)rnb;
    }

    // ---- Output phase (8 iters) ----
#pragma unroll
    for (int j = 0; j < L; ++j) {
        int ia = da0 + Wb + j, ib = db0 + Wb + j;
        float c1a = s1[padi(ia)], c2a = s2[padi(ia)];
        float c1b = s1[padi(ib)], c2b = s2[padi(ib)];
        float qda = fmaxf(c2a + gwa, 0.0f);   // uses OLD gw
        float qdb = fmaxf(c2b + gwb, 0.0f);
        DUAL_STEP(c1a, c1b)
        sq[padi(da0 + j)] = (sa - rna) + qda;
        sr[padi(da0 + j)] = rna;
        sq[padi(db0 + j)] = (sb - rnb) + qdb;
        sr[padi(db0 + j)] = rnb;
    }
    __syncthreads();

    // ---- Coalesced epilogue ----
    float* __restrict__ qout = out;        // qsim    [0, T)
    float* __restrict__ rout = out + T;    // r_store [T, 2T)
    int lim = T - t0b; if (lim > OSZ) lim = OSZ;
    for (int d = tid; d < lim; d += BLK) {
        qout[t0b + d] = sq[padi(d)];
        rout[t0b + d] = sr[padi(d)];
    }
}

extern "C" void kernel_launch(void* const* d_in, const int* in_sizes, int n_in,
                              void* d_out, int out_size) {
    const float* x  = (const float*)d_in[0];
    const float* x2 = (const float*)d_in[1];
    const float* x3 = (const float*)d_in[2];
    int T = in_sizes[0] / 4;
    if (T > T_MAX) T = T_MAX;

    int NTOT = FRONT + T + BACK;
    conv_kernel<<<(NTOT + 255) / 256, 256>>>(x, T, NTOT);
    solve_kernel<<<1, 256>>>(x2, x3, T);

    int nblocks = (T + OSZ - 1) / OSZ;     // 512 for T = 262144
    scan_kernel<<<nblocks, BLK>>>(x2, x3, (float*)d_out, T);
}

// round 14
// speedup vs baseline: 7.2393x; 1.0784x over previous
#include <cuda_runtime.h>
#include <math.h>

// ---------------------------------------------------------------------------
// RoutingStorage (GR4J). Chunk-parallel scan, warm-started warmup.
// R14 = R13's validated scan numerics (W_ZERO=208 block0, W_WARM=160,
// WARM_T0=416 -> rel_err 6.1e-5) with the auxiliaries fixed:
//  - conv: smem-staged pr (1 float4 load/elem instead of 6) -> ~1.5us
//  - solve: 32 fixed-point iters from z=45 (warmup contracts r^ error 6e-4x)
// Scan wall = block0's 216 iters (ramp chains need ~150 ramp + ~60
// contraction steps; irreducible under zero-start).
// ---------------------------------------------------------------------------

#define T_MAX 262144
constexpr int L       = 8;     // output steps per chain
constexpr int W_WARM  = 160;   // warmup, warm-started blocks (b >= 1)
constexpr int W_ZERO  = 208;   // warmup, block 0 (zero-start region)
constexpr int FRONT   = W_ZERO;
constexpr int BACK    = 64;
constexpr int BLK     = 32;    // threads/block (1 warp), 2 chains/thread
constexpr int CPB     = BLK * 2;             // 64 chains/block
constexpr int OSZ     = CPB * L;             // 512 outputs/block
constexpr int WSZ     = W_ZERO + OSZ;        // 720 max window
constexpr int WSZP    = WSZ + WSZ / 32;
constexpr int OSZP    = OSZ + OSZ / 32;
constexpr int WARM_T0 = 416;   // chains with t0 >= this warm-start from r^

static __device__ float  g_c1[FRONT + T_MAX + BACK];
static __device__ float  g_c2[FRONT + T_MAX + BACK];
static __device__ float2 g_init;     // (z0 = r^+gw^, gw^)

__device__ __forceinline__ float fsqrt_approx(float x) {
    float y; asm("sqrt.approx.f32 %0, %1;" : "=f"(y) : "f"(x)); return y;
}
__device__ __forceinline__ int padi(int d) { return d + (d >> 5); }

// Unit-hydrograph ordinates for X4 = 2.5:
__constant__ float c_o1[3] = {0.10119288512538814f, 0.47124051711455807f,
                              0.42756659776005380f};
__constant__ float c_o2[6] = {0.05059644256269407f, 0.23562025855727903f,
                              0.42756659776005380f, 0.23562025855727903f,
                              0.05059644256269407f, 0.0f};

// Conv with smem-staged pr: one float4 load per element (was 6).
__global__ void conv_kernel(const float* __restrict__ x, int T, int NTOT) {
    __shared__ float spr[256 + 8];
    int base = blockIdx.x * 256;            // output i-range [base, base+256)
    int tid  = threadIdx.x;
    int tw0  = base - FRONT - 5;            // t of spr[0]
    for (int d = tid; d < 256 + 5; d += 256) {
        int t = tw0 + d;
        float pr = 0.0f;
        if (t >= 0 && t < T) {
            float4 row = *reinterpret_cast<const float4*>(x + 4 * t);
            pr = row.w + (row.x - row.z);   // perc + (p_n - p_s)
        }
        spr[d] = pr;
    }
    __syncthreads();
    int i = base + tid;
    if (i >= NTOT) return;
    int t = i - FRONT;
    if (t < 0 || t >= T) { g_c1[i] = 0.0f; g_c2[i] = 0.0f; return; }
    float c1 = 0.0f, c2 = 0.0f;
#pragma unroll
    for (int j = 0; j < 6; ++j) {
        float pr = spr[tid + 5 - j];        // = pr(t - j)
        if (j < 3) c1 += c_o1[j] * (0.9f * pr);
        c2 += c_o2[j] * (0.1f * pr);
    }
    g_c1[i] = c1; g_c2[i] = c2;
}

// (1+u)^(-1/4) deg-4 Horner
#define P1 (-0.25f)
#define P2 ( 0.15625f)
#define P3 (-0.1171875f)
#define P4 ( 0.0952148438f)
// (1+u)^(-7/8) deg-3 Horner (off-critical gw branch)
#define Q1 (-0.875f)
#define Q2 ( 0.8203125f)
#define Q3 (-0.7861328125f)

// Sampled mean inflow -> fast approx fixed-point for the stationary store.
__global__ void solve_kernel(const float* __restrict__ x2p,
                             const float* __restrict__ x3p, int T) {
    __shared__ float red[256];
    int nsamp = T / 64; if (nsamp < 1) nsamp = 1;
    float s = 0.0f;
    for (int k = threadIdx.x; k < nsamp; k += 256)
        s += g_c1[FRONT + 64 * k];
    red[threadIdx.x] = s;
    __syncthreads();
#pragma unroll
    for (int w = 128; w > 0; w >>= 1) {
        if (threadIdx.x < w) red[threadIdx.x] += red[threadIdx.x + w];
        __syncthreads();
    }
    if (threadIdx.x == 0) {
        float m   = red[0] / (float)nsamp;
        float x2  = x2p[0], x3 = x3p[0];
        float inv = 1.0f / x3;
        float inv2 = inv * inv, inv4 = inv2 * inv2;
        float kx  = __powf(x2, 0.2857142857f) * inv;
        float z = 45.0f, gw = 0.0f;
        for (int it = 0; it < 32; ++it) {
            float sv_ = fmaxf(z + m, 0.0f);
            float v   = sv_ * kx;
            float sq  = fsqrt_approx(v);
            float a   = sv_ * sv_;
            float u   = (a * inv4) * a;
            float p   = fmaf(u, P4, P3); p = fmaf(u, p, P2);
            p = fmaf(u, p, P1); p = fmaf(u, p, 1.0f);
            float qq  = fmaf(u, Q3, Q2);
            qq = fmaf(u, qq, Q1); qq = fmaf(u, qq, 1.0f);
            float rn  = sv_ * p;
            gw = (((v * v) * v) * sq) * qq;
            z  = rn + gw;
        }
        g_init = make_float2(z, gw);
    }
}

// Stage-ordered dual-chain step core. Updates za,gwa,zb,gwb;
// exposes sa,sb,rna,rnb. (Validated numerics — unchanged.)
#define DUAL_STEP(c1a, c1b)                                            \
    float sa  = fmaxf(za + c1a, 0.0f), sb  = fmaxf(zb + c1b, 0.0f);    \
    float va  = sa * kx,               vb  = sb * kx;                  \
    float sva = fsqrt_approx(va),      svb = fsqrt_approx(vb);         \
    float aa  = sa * sa,               ab  = sb * sb;                  \
    float ua  = (aa * inv4) * aa,      ub  = (ab * inv4) * ab;         \
    float pa  = fmaf(ua, P4, P3),      pb  = fmaf(ub, P4, P3);         \
    pa = fmaf(ua, pa, P2);             pb = fmaf(ub, pb, P2);          \
    pa = fmaf(ua, pa, P1);             pb = fmaf(ub, pb, P1);          \
    pa = fmaf(ua, pa, 1.0f);           pb = fmaf(ub, pb, 1.0f);        \
    float qa = fmaf(ua, Q3, Q2),       qb = fmaf(ub, Q3, Q2);          \
    qa = fmaf(ua, qa, Q1);             qb = fmaf(ub, qb, Q1);          \
    qa = fmaf(ua, qa, 1.0f);           qb = fmaf(ub, qb, 1.0f);        \
    float ga  = ((va * va) * va) * sva, gb = ((vb * vb) * vb) * svb;   \
    float rna = sa * pa,               rnb = sb * pb;                  \
    gwa = ga * qa;                     gwb = gb * qb;                  \
    za  = rna + gwa;                   zb  = rnb + gwb;

__global__ void __launch_bounds__(BLK, 1)
scan_kernel(const float* __restrict__ x2p,
            const float* __restrict__ x3p,
            float* __restrict__ out, int T) {
    __shared__ float s1[WSZP];
    __shared__ float s2[WSZP];
    __shared__ float sq[OSZP];
    __shared__ float sr[OSZP];

    int tid = threadIdx.x;
    int b   = blockIdx.x;
    int t0b = b * OSZ;
    if (t0b >= T) return;

    const int Wb  = (b == 0) ? W_ZERO : W_WARM;
    const int wsz = Wb + OSZ;
    {
        int gbase = t0b + FRONT - Wb;
        const float* g1 = g_c1 + gbase;
        const float* g2 = g_c2 + gbase;
        for (int d = tid; d < wsz; d += BLK) {
            s1[padi(d)] = g1[d];
            s2[padi(d)] = g2[d];
        }
    }
    __syncthreads();

    const float x2  = __ldg(x2p);
    const float x3  = __ldg(x3p);
    const float inv = 1.0f / x3;
    const float inv2 = inv * inv, inv4 = inv2 * inv2;
    const float kx  = __powf(x2, 0.2857142857f) * inv;   // x2^(2/7)/x3

    // Chain A: t0 = t0b + 8*tid; chain B: t0 + 256.
    const int da0 = tid * L;
    const int db0 = da0 + 256;
    const int t0a = t0b + da0;
    const int t0c = t0a + 256;

    float2 init = g_init;
    float za, gwa, zb, gwb;
    if (t0a >= WARM_T0) { za = init.x; gwa = init.y; } else { za = 0.0f; gwa = 0.0f; }
    if (t0c >= WARM_T0) { zb = init.x; gwb = init.y; } else { zb = 0.0f; gwb = 0.0f; }

    // ---- Warmup: software-pipelined c1 loads (prefetch depth 1) ----
    float n1a = s1[padi(da0)];
    float n1b = s1[padi(db0)];
#pragma unroll 8
    for (int i = 0; i < Wb; ++i) {
        float c1a = n1a, c1b = n1b;
        n1a = s1[padi(da0 + i + 1)];      // next iter's inputs: LDS latency
        n1b = s1[padi(db0 + i + 1)];      // overlaps this iter's math
        DUAL_STEP(c1a, c1b)
        (void)rna; (void)rnb;
    }

    // ---- Output phase (8 iters) ----
#pragma unroll
    for (int j = 0; j < L; ++j) {
        int ia = da0 + Wb + j, ib = db0 + Wb + j;
        float c1a = s1[padi(ia)], c2a = s2[padi(ia)];
        float c1b = s1[padi(ib)], c2b = s2[padi(ib)];
        float qda = fmaxf(c2a + gwa, 0.0f);   // uses OLD gw
        float qdb = fmaxf(c2b + gwb, 0.0f);
        DUAL_STEP(c1a, c1b)
        sq[padi(da0 + j)] = (sa - rna) + qda;
        sr[padi(da0 + j)] = rna;
        sq[padi(db0 + j)] = (sb - rnb) + qdb;
        sr[padi(db0 + j)] = rnb;
    }
    __syncthreads();

    // ---- Coalesced epilogue ----
    float* __restrict__ qout = out;        // qsim    [0, T)
    float* __restrict__ rout = out + T;    // r_store [T, 2T)
    int lim = T - t0b; if (lim > OSZ) lim = OSZ;
    for (int d = tid; d < lim; d += BLK) {
        qout[t0b + d] = sq[padi(d)];
        rout[t0b + d] = sr[padi(d)];
    }
}

extern "C" void kernel_launch(void* const* d_in, const int* in_sizes, int n_in,
                              void* d_out, int out_size) {
    const float* x  = (const float*)d_in[0];
    const float* x2 = (const float*)d_in[1];
    const float* x3 = (const float*)d_in[2];
    int T = in_sizes[0] / 4;
    if (T > T_MAX) T = T_MAX;

    int NTOT = FRONT + T + BACK;
    conv_kernel<<<(NTOT + 255) / 256, 256>>>(x, T, NTOT);
    solve_kernel<<<1, 256>>>(x2, x3, T);

    int nblocks = (T + OSZ - 1) / OSZ;     // 512 for T = 262144
    scan_kernel<<<nblocks, BLK>>>(x2, x3, (float*)d_out, T);
}

// round 15
// speedup vs baseline: 9.0898x; 1.2556x over previous
#include <cuda_runtime.h>
#include <math.h>

// ---------------------------------------------------------------------------
// RoutingStorage (GR4J). Chunk-parallel scan, warm-started warmup.
// R15: conv kernel ELIMINATED (it was wave-transition/launch bound at 5.7us,
// not load bound) -- the FIR is fused into each scan block's smem staging
// phase (read raw x window coalesced, pr -> smem, 3/5-tap FIR -> s1/s2).
// Solve samples x directly. Accuracy margin spent: W_ZERO 208->176
// (block-0 wall 216->184 iters). Validated numerics otherwise unchanged
// (W_WARM=160, WARM_T0=416, dual-chain stage-ordered step).
// ---------------------------------------------------------------------------

#define T_MAX 262144
constexpr int L       = 8;     // output steps per chain
constexpr int W_WARM  = 160;   // warmup, warm-started blocks (b >= 1)
constexpr int W_ZERO  = 176;   // warmup, block 0 (zero-start region)
constexpr int BLK     = 32;    // threads/block (1 warp), 2 chains/thread
constexpr int CPB     = BLK * 2;             // 64 chains/block
constexpr int OSZ     = CPB * L;             // 512 outputs/block
constexpr int WSZ     = W_ZERO + OSZ;        // 688 max window
constexpr int WSZP    = WSZ + WSZ / 32;      // 709
constexpr int OSZP    = OSZ + OSZ / 32;      // 528
constexpr int SPRN    = WSZ + 5;             // 693 raw pr window
constexpr int WARM_T0 = 416;   // chains with t0 >= this warm-start from r^

static __device__ float2 g_init;     // (z0 = r^+gw^, gw^)

__device__ __forceinline__ float fsqrt_approx(float x) {
    float y; asm("sqrt.approx.f32 %0, %1;" : "=f"(y) : "f"(x)); return y;
}
__device__ __forceinline__ int padi(int d) { return d + (d >> 5); }

// Unit-hydrograph ordinates for X4 = 2.5 (o2[5] = 0 exactly):
#define O1_0 0.10119288512538814f
#define O1_1 0.47124051711455807f
#define O1_2 0.42756659776005380f
#define O2_0 0.05059644256269407f
#define O2_1 0.23562025855727903f
#define O2_2 0.42756659776005380f
#define O2_3 0.23562025855727903f
#define O2_4 0.05059644256269407f

// (1+u)^(-1/4) deg-4 Horner
#define P1 (-0.25f)
#define P2 ( 0.15625f)
#define P3 (-0.1171875f)
#define P4 ( 0.0952148438f)
// (1+u)^(-7/8) deg-3 Horner (off-critical gw branch)
#define Q1 (-0.875f)
#define Q2 ( 0.8203125f)
#define Q3 (-0.7861328125f)

// Sample mean inflow from x directly -> fast fixed-point for stationary store.
__global__ void solve_kernel(const float* __restrict__ x,
                             const float* __restrict__ x2p,
                             const float* __restrict__ x3p, int T) {
    __shared__ float red[256];
    int nsamp = T / 256; if (nsamp < 1) nsamp = 1;
    float s = 0.0f;
    for (int k = threadIdx.x; k < nsamp; k += 256) {
        float4 row = *reinterpret_cast<const float4*>(x + 4 * (256 * k));
        s += row.w + (row.x - row.z);      // pr sample
    }
    red[threadIdx.x] = s;
    __syncthreads();
#pragma unroll
    for (int w = 128; w > 0; w >>= 1) {
        if (threadIdx.x < w) red[threadIdx.x] += red[threadIdx.x + w];
        __syncthreads();
    }
    if (threadIdx.x == 0) {
        float m   = 0.9f * red[0] / (float)nsamp;   // mean pr1 = mean c1
        float x2  = x2p[0], x3 = x3p[0];
        float inv = 1.0f / x3;
        float inv2 = inv * inv, inv4 = inv2 * inv2;
        float kx  = __powf(x2, 0.2857142857f) * inv;
        float z = 45.0f, gw = 0.0f;
        for (int it = 0; it < 32; ++it) {
            float sv_ = fmaxf(z + m, 0.0f);
            float v   = sv_ * kx;
            float sq  = fsqrt_approx(v);
            float a   = sv_ * sv_;
            float u   = (a * inv4) * a;
            float p   = fmaf(u, P4, P3); p = fmaf(u, p, P2);
            p = fmaf(u, p, P1); p = fmaf(u, p, 1.0f);
            float qq  = fmaf(u, Q3, Q2);
            qq = fmaf(u, qq, Q1); qq = fmaf(u, qq, 1.0f);
            float rn  = sv_ * p;
            gw = (((v * v) * v) * sq) * qq;
            z  = rn + gw;
        }
        g_init = make_float2(z, gw);
    }
}

// Stage-ordered dual-chain step core. Updates za,gwa,zb,gwb;
// exposes sa,sb,rna,rnb. (Validated numerics — unchanged.)
#define DUAL_STEP(c1a, c1b)                                            \
    float sa  = fmaxf(za + c1a, 0.0f), sb  = fmaxf(zb + c1b, 0.0f);    \
    float va  = sa * kx,               vb  = sb * kx;                  \
    float sva = fsqrt_approx(va),      svb = fsqrt_approx(vb);         \
    float aa  = sa * sa,               ab  = sb * sb;                  \
    float ua  = (aa * inv4) * aa,      ub  = (ab * inv4) * ab;         \
    float pa  = fmaf(ua, P4, P3),      pb  = fmaf(ub, P4, P3);         \
    pa = fmaf(ua, pa, P2);             pb = fmaf(ub, pb, P2);          \
    pa = fmaf(ua, pa, P1);             pb = fmaf(ub, pb, P1);          \
    pa = fmaf(ua, pa, 1.0f);           pb = fmaf(ub, pb, 1.0f);        \
    float qa = fmaf(ua, Q3, Q2),       qb = fmaf(ub, Q3, Q2);          \
    qa = fmaf(ua, qa, Q1);             qb = fmaf(ub, qb, Q1);          \
    qa = fmaf(ua, qa, 1.0f);           qb = fmaf(ub, qb, 1.0f);        \
    float ga  = ((va * va) * va) * sva, gb = ((vb * vb) * vb) * svb;   \
    float rna = sa * pa,               rnb = sb * pb;                  \
    gwa = ga * qa;                     gwb = gb * qb;                  \
    za  = rna + gwa;                   zb  = rnb + gwb;

__global__ void __launch_bounds__(BLK, 1)
scan_kernel(const float* __restrict__ x,
            const float* __restrict__ x2p,
            const float* __restrict__ x3p,
            float* __restrict__ out, int T) {
    __shared__ float spr[SPRN];
    __shared__ float s1[WSZP];
    __shared__ float s2[OSZP];     // c2 only for the output range
    __shared__ float sq[OSZP];
    __shared__ float sr[OSZP];

    int tid = threadIdx.x;
    int b   = blockIdx.x;
    int t0b = b * OSZ;
    if (t0b >= T) return;

    const int Wb  = (b == 0) ? W_ZERO : W_WARM;
    const int wsz = Wb + OSZ;

    // ---- Fused conv staging ----
    // spr[k] = pr(pt0 + k), pt0 = t0b - Wb - 5 (zeros outside [0, T)).
    {
        int pt0 = t0b - Wb - 5;
        for (int k = tid; k < wsz + 5; k += BLK) {
            int t = pt0 + k;
            float pr = 0.0f;
            if (t >= 0 && t < T) {
                float4 row = *reinterpret_cast<const float4*>(x + 4 * t);
                pr = row.w + (row.x - row.z);   // perc + (p_n - p_s)
            }
            spr[k] = pr;
        }
        __syncthreads();
        // c1 over the whole window; window offset d -> time t0b - Wb + d.
        for (int d = tid; d < wsz; d += BLK) {
            float c1 = 0.9f * (O1_0 * spr[d + 5] + O1_1 * spr[d + 4]
                             + O1_2 * spr[d + 3]);
            s1[padi(d)] = c1;
        }
        // c2 only for the output range d in [Wb, wsz), stored at d - Wb.
        for (int d = tid; d < OSZ; d += BLK) {
            int k = d + Wb;
            float c2 = 0.1f * (O2_0 * spr[k + 5] + O2_1 * spr[k + 4]
                             + O2_2 * spr[k + 3] + O2_3 * spr[k + 2]
                             + O2_4 * spr[k + 1]);
            s2[padi(d)] = c2;
        }
    }
    __syncthreads();

    const float x2  = __ldg(x2p);
    const float x3  = __ldg(x3p);
    const float inv = 1.0f / x3;
    const float inv2 = inv * inv, inv4 = inv2 * inv2;
    const float kx  = __powf(x2, 0.2857142857f) * inv;   // x2^(2/7)/x3

    // Chain A: t0 = t0b + 8*tid; chain B: t0 + 256.
    const int da0 = tid * L;
    const int db0 = da0 + 256;
    const int t0a = t0b + da0;
    const int t0c = t0a + 256;

    float2 init = g_init;
    float za, gwa, zb, gwb;
    if (t0a >= WARM_T0) { za = init.x; gwa = init.y; } else { za = 0.0f; gwa = 0.0f; }
    if (t0c >= WARM_T0) { zb = init.x; gwb = init.y; } else { zb = 0.0f; gwb = 0.0f; }

    // ---- Warmup: software-pipelined c1 loads (prefetch depth 1) ----
    float n1a = s1[padi(da0)];
    float n1b = s1[padi(db0)];
#pragma unroll 8
    for (int i = 0; i < Wb; ++i) {
        float c1a = n1a, c1b = n1b;
        n1a = s1[padi(da0 + i + 1)];      // next iter's input: LDS latency
        n1b = s1[padi(db0 + i + 1)];      // overlaps this iter's math
        DUAL_STEP(c1a, c1b)
        (void)rna; (void)rnb;
    }

    // ---- Output phase (8 iters) ----
#pragma unroll
    for (int j = 0; j < L; ++j) {
        int ia = da0 + Wb + j, ib = db0 + Wb + j;
        float c1a = s1[padi(ia)], c2a = s2[padi(da0 + j)];
        float c1b = s1[padi(ib)], c2b = s2[padi(db0 + j)];
        float qda = fmaxf(c2a + gwa, 0.0f);   // uses OLD gw
        float qdb = fmaxf(c2b + gwb, 0.0f);
        DUAL_STEP(c1a, c1b)
        sq[padi(da0 + j)] = (sa - rna) + qda;
        sr[padi(da0 + j)] = rna;
        sq[padi(db0 + j)] = (sb - rnb) + qdb;
        sr[padi(db0 + j)] = rnb;
    }
    __syncthreads();

    // ---- Coalesced epilogue ----
    float* __restrict__ qout = out;        // qsim    [0, T)
    float* __restrict__ rout = out + T;    // r_store [T, 2T)
    int lim = T - t0b; if (lim > OSZ) lim = OSZ;
    for (int d = tid; d < lim; d += BLK) {
        qout[t0b + d] = sq[padi(d)];
        rout[t0b + d] = sr[padi(d)];
    }
}

extern "C" void kernel_launch(void* const* d_in, const int* in_sizes, int n_in,
                              void* d_out, int out_size) {
    const float* x  = (const float*)d_in[0];
    const float* x2 = (const float*)d_in[1];
    const float* x3 = (const float*)d_in[2];
    int T = in_sizes[0] / 4;
    if (T > T_MAX) T = T_MAX;

    solve_kernel<<<1, 256>>>(x, x2, x3, T);

    int nblocks = (T + OSZ - 1) / OSZ;     // 512 for T = 262144
    scan_kernel<<<nblocks, BLK>>>(x, x2, x3, (float*)d_out, T);
}